// round 15
// baseline (speedup 1.0000x reference)
#include <cuda_runtime.h>
#include <cuda_bf16.h>
#include <math.h>

// ---------------- problem constants ----------------
#define NB    16
#define NS    256
#define HD    384     // H
#define HD2   1536    // H2
#define NHEAD 2
#define DH    192     // H / NHEAD
#define KW    3
#define NLAY  4
#define TOUT  1024
#define MEL   80

typedef __nv_bfloat16  bf16;
typedef __nv_bfloat162 bf162;

// Is this device pass an sm_103a-specific (tcgen05-capable) compilation?
#if defined(__CUDA_ARCH__) && (defined(__CUDA_ARCH_FEAT_SM103_ALL) || \
    (defined(__CUDA_ARCH_SPECIFIC__) && (__CUDA_ARCH_SPECIFIC__ == 1030)))
#define TC5 1
#else
#define TC5 0
#endif

// ---------------- fp32 scratch ----------------
__device__ float g_x [NB*NS*HD];
__device__ float g_y [NB*TOUT*HD];
__device__ float g_u [NB*TOUT*HD];
__device__ float g_sf[NB*NHEAD*TOUT*TOUT];
__device__ float g_ha[NB*NS*HD];
__device__ float g_hb[NB*NS*HD];
__device__ int   g_cum[NB*NS];

// ---------------- bf16 hi/lo planes ----------------
#define DECL2(name, sz) \
    __device__ __align__(16) bf16 name##_h[sz]; \
    __device__ __align__(16) bf16 name##_l[sz]
DECL2(g_wa,  8*4*HD*HD);
DECL2(g_w1,  8*HD2*KW*HD);
DECL2(g_w2,  8*HD*KW*HD2);
DECL2(g_wal, 2*HD*KW*HD);
DECL2(g_wm,  MEL*HD);
DECL2(g_xs,  NB*TOUT*HD);
DECL2(g_qk,  2*NB*TOUT*HD);
DECL2(g_vs,  NB*HD*TOUT);
DECL2(g_ss,  NB*NHEAD*TOUT*TOUT);
DECL2(g_ts,  NB*TOUT*HD);
DECL2(g_hs,  NB*TOUT*HD2);

// ---------------- helpers ----------------
__device__ __forceinline__ void fsplit(float v, bf16& h, bf16& l) {
    h = __float2bfloat16(v);
    l = __float2bfloat16(v - __bfloat162float(h));
}

__device__ __forceinline__ float pe_val(int t, int h) {
    int i2 = (h >> 1) * 2;
    float den = expf(-9.210340371976184f * (float)i2 / (float)HD);
    float ang = (float)t * den;
    return (h & 1) ? cosf(ang) : sinf(ang);
}

__device__ __forceinline__ void cpa16(unsigned dst, const void* src, bool pred) {
    int sz = pred ? 16 : 0;                 // src-size 0 -> 16B zero-fill
    asm volatile("cp.async.cg.shared.global [%0], [%1], 16, %2;"
                 :: "r"(dst), "l"(src), "r"(sz));
}
__device__ __forceinline__ void cpa_commit() { asm volatile("cp.async.commit_group;"); }
__device__ __forceinline__ void cpa_wait0()  { asm volatile("cp.async.wait_group 0;"); }
__device__ __forceinline__ void cpa_wait1()  { asm volatile("cp.async.wait_group 1;"); }

// ---- mma.sync helpers (valid on plain sm_103) ----
__device__ __forceinline__ void mma_bf16(float* d, unsigned a0, unsigned a1,
                                         unsigned a2, unsigned a3,
                                         unsigned b0, unsigned b1) {
    asm volatile(
        "mma.sync.aligned.m16n8k16.row.col.f32.bf16.bf16.f32 "
        "{%0,%1,%2,%3},{%4,%5,%6,%7},{%8,%9},{%0,%1,%2,%3};"
        : "+f"(d[0]), "+f"(d[1]), "+f"(d[2]), "+f"(d[3])
        : "r"(a0), "r"(a1), "r"(a2), "r"(a3), "r"(b0), "r"(b1));
}
__device__ __forceinline__ void ldsm_x4(unsigned& r0, unsigned& r1, unsigned& r2,
                                        unsigned& r3, unsigned addr) {
    asm volatile("ldmatrix.sync.aligned.m8n8.x4.shared.b16 {%0,%1,%2,%3}, [%4];"
                 : "=r"(r0), "=r"(r1), "=r"(r2), "=r"(r3) : "r"(addr));
}

#if TC5
// ---- tcgen05 helpers (sm_103a-only pass) ----
__device__ __forceinline__ void mbar_wait(unsigned mbar, int parity) {
    asm volatile(
        "{\n\t.reg .pred P1;\n\t"
        "WL%=:\n\t"
        "mbarrier.try_wait.parity.acquire.cta.shared::cta.b64 P1, [%0], %1, 0x989680;\n\t"
        "@P1 bra.uni WD%=;\n\t"
        "bra.uni WL%=;\n\t"
        "WD%=:\n\t}"
        :: "r"(mbar), "r"(parity) : "memory");
}
// idesc: kind::f16, bf16 inputs, fp32 accum, M=128, N=128 (per accumulator)
#define IDESC_TC ((1u<<4)|(1u<<7)|(1u<<10)|((128u/8)<<17)|((128u/16)<<24))
__device__ __forceinline__ unsigned long long make_desc(unsigned addr) {
    const unsigned long long base =
        (2ULL << 61) | (1ULL << 46) | (64ULL << 32) | (1ULL << 16);  // SW128
    return base | ((unsigned long long)(addr >> 4) & 0x3FFFULL);
}
__device__ __forceinline__ void mma_ss_f16(unsigned dtmem, unsigned long long ad,
                                           unsigned long long bd, unsigned en) {
    asm volatile(
        "{\n\t.reg .pred p;\n\t"
        "setp.ne.u32 p, %5, 0;\n\t"
        "tcgen05.mma.cta_group::1.kind::f16 [%0], %1, %2, %3, {%4,%4,%4,%4}, p;\n\t}"
        :: "r"(dtmem), "l"(ad), "l"(bd), "r"(IDESC_TC), "r"(0u), "r"(en)
        : "memory");
}
__device__ __forceinline__ void ldtm32(unsigned* r, unsigned a) {
    asm volatile(
        "tcgen05.ld.sync.aligned.32x32b.x32.b32 "
        "{%0,%1,%2,%3,%4,%5,%6,%7,%8,%9,%10,%11,%12,%13,%14,%15,"
        "%16,%17,%18,%19,%20,%21,%22,%23,%24,%25,%26,%27,%28,%29,%30,%31}, [%32];"
        : "=r"(r[0]),  "=r"(r[1]),  "=r"(r[2]),  "=r"(r[3]),
          "=r"(r[4]),  "=r"(r[5]),  "=r"(r[6]),  "=r"(r[7]),
          "=r"(r[8]),  "=r"(r[9]),  "=r"(r[10]), "=r"(r[11]),
          "=r"(r[12]), "=r"(r[13]), "=r"(r[14]), "=r"(r[15]),
          "=r"(r[16]), "=r"(r[17]), "=r"(r[18]), "=r"(r[19]),
          "=r"(r[20]), "=r"(r[21]), "=r"(r[22]), "=r"(r[23]),
          "=r"(r[24]), "=r"(r[25]), "=r"(r[26]), "=r"(r[27]),
          "=r"(r[28]), "=r"(r[29]), "=r"(r[30]), "=r"(r[31])
        : "r"(a));
}
#define SWZ(o) ((o) ^ (((o) >> 3) & 0x70))
#endif  // TC5

// ---------------- weight transpose + split: in [K][N] fp32 -> planes [N][K] ----
__global__ void tsplit_k(const float* __restrict__ in, bf16* __restrict__ oh,
                         bf16* __restrict__ ol, int K, int N) {
    __shared__ float t[32][33];
    long stride = (long)K * N;
    const float* ib = in + blockIdx.z * stride;
    bf16* ohb = oh + blockIdx.z * stride;
    bf16* olb = ol + blockIdx.z * stride;
    int k0 = blockIdx.y * 32, n0 = blockIdx.x * 32;
    int tx = threadIdx.x, ty = threadIdx.y;
    for (int i = 0; i < 32; i += 8) {
        int k = k0 + ty + i, n = n0 + tx;
        t[ty + i][tx] = (k < K && n < N) ? ib[(long)k * N + n] : 0.f;
    }
    __syncthreads();
    for (int i = 0; i < 32; i += 8) {
        int n = n0 + ty + i, k = k0 + tx;
        if (n < N && k < K) {
            bf16 h, l; fsplit(t[tx][ty + i], h, l);
            ohb[(long)n * K + k] = h;
            olb[(long)n * K + k] = l;
        }
    }
}

// ---------------- embed + posenc ----------------
__global__ void embed_k(const int* __restrict__ tok, const float* __restrict__ emb,
                        float* __restrict__ x, bf16* __restrict__ sh,
                        bf16* __restrict__ sl) {
    int bt = blockIdx.x;
    int t  = bt % NS;
    int v  = tok[bt];
    const float* e = emb + (long)v * HD;
    long base = (long)bt * HD;
    for (int i = threadIdx.x; i < HD; i += blockDim.x) {
        float val = e[i] * 19.595917942265423f + pe_val(t, i);
        x[base + i] = val;
        bf16 h, l; fsplit(val, h, l);
        sh[base + i] = h; sl[base + i] = l;
    }
}

// ---------------- unified NT bf16 GEMM (3-term split) ----------------
// C = alpha * A @ B^T (+bias) (opt relu); A [m][k] planes pitch pA,
// B [n][k] planes pitch pB. batching: z=g; gq_=g/gdiv, gr_=g%gdiv.
// CONV=1: A row m -> time tp = m0+m-1+kw, kw = k0/pA.
// EPI: 0 = fp32 C, 1 = split planes [m][n], 2 = split planes transposed [n][m].
// Tiles: 128 x 256 (tcgen05 dual-accumulator, 2-stage pipe) /
//        128 x (4x64) (fallback). M%128==0, Kd%64==0, Kd>=192, N even.
#define SMEM_BYTES 197632
// mma.sync fallback layout
#define SKP 20
#define A_WORDS  (2*128*SKP)
#define B_WORDS  (2*64*SKP)
#define ABUF (128*SKP)
#define BBUF (64*SKP)
// tcgen05 layout: stage = A(32KB) + B0(32KB) + B1(32KB) = 96KB, 2 stages
#define STAGE_BYTES 98304
#define SM_A_L  16384
#define SM_B0H  32768
#define SM_B0L  49152
#define SM_B1H  65536
#define SM_B1L  81920

template<int CONV, int EPI>
__global__ __launch_bounds__(256, 1) __cluster_dims__(1, 1, 1)
void gemm_bf(
    const bf16* __restrict__ Ah, const bf16* __restrict__ Al,
    int gdiv, long a1, long a2, int pA,
    const bf16* __restrict__ Bh, const bf16* __restrict__ Bl,
    long b1, long b2, int pB,
    const float* __restrict__ bias, long bstr,
    float* __restrict__ C, long c1, long c2, int cRow, int cCol,
    bf16* __restrict__ Sh, bf16* __restrict__ Sl, int sPitch,
    int M, int N, int Kd, float alpha, int relu)
{
    extern __shared__ unsigned smw[];

    int g = blockIdx.z;
    int gq_ = g / gdiv, gr_ = g % gdiv;
    const bf16* Abh = Ah + gq_ * a1 + gr_ * a2;
    const bf16* Abl = Al + gq_ * a1 + gr_ * a2;
    const bf16* Bbh = Bh + gq_ * b1 + gr_ * b2;
    const bf16* Bbl = Bl + gq_ * b1 + gr_ * b2;
    long coff = gq_ * c1 + gr_ * c2;
    const float* bias_e = bias ? bias + gq_ * bstr : (const float*)0;

    int m0 = blockIdx.y * 128, n0 = blockIdx.x * 256;
    int tid = threadIdx.x, lane = tid & 31, wid = tid >> 5;

#if TC5
    // ===== tcgen05 path (sm_103a): 128x256 tile, dual accumulators =====
    unsigned sm0 = (unsigned)__cvta_generic_to_shared(smw);
    unsigned base = (sm0 + 1023u) & ~1023u;
    unsigned tptr = base;
    unsigned mbb  = base + 8;          // mb[j] = mbb + 8*j, j=0..1
    unsigned tiles = base + 1024;

    int act1 = (n0 + 128) < N;

    if (wid == 0) {
        asm volatile("tcgen05.alloc.cta_group::1.sync.aligned.shared::cta.b32 [%0], %1;"
                     :: "r"(tptr), "r"(256u) : "memory");
    }
    if (tid == 0) {
#pragma unroll
        for (int j = 0; j < 2; j++)
            asm volatile("mbarrier.init.shared.b64 [%0], %1;"
                         :: "r"(mbb + 8u * j), "r"(1u) : "memory");
    }
    __syncthreads();
    if (wid == 0)
        asm volatile("tcgen05.relinquish_alloc_permit.cta_group::1.sync.aligned;");
    unsigned tmem;
    asm volatile("ld.shared.b32 %0, [%1];" : "=r"(tmem) : "r"(tptr));

    int nt = Kd >> 6;   // >= 3 for all GEMMs in this network

    auto issueLoads = [&](int s) {            // stage s -> buffer s%2
        int k0 = s << 6;
        unsigned tb = tiles + (unsigned)(s & 1) * STAGE_BYTES;
        int row = tid >> 1;               // 0..127
        int cbase = (tid & 1) * 4;        // 4 x 16B chunks per thread per plane
        // A
        long ra = 0; bool ok = true;
        if (CONV) {
            int kw = k0 / pA;
            int co = k0 - kw * pA;
            int tp = m0 + row - 1 + kw;
            ok = (tp >= 0 && tp < M);
            ra = ok ? (long)tp * pA + co : 0;
        } else {
            ra = (long)(m0 + row) * pA + k0;
        }
#pragma unroll
        for (int j = 0; j < 4; j++) {
            int c = cbase + j;
            unsigned d = tb + SWZ((unsigned)(row * 128 + c * 16));
            cpa16(d,          Abh + ra + c * 8, ok);
            cpa16(d + SM_A_L, Abl + ra + c * 8, ok);
        }
        // B0: rows n0..n0+127
        bool okb0 = (n0 + row) < N;
        long rB0 = okb0 ? (long)(n0 + row) * pB + k0 : 0;
        // B1: rows n0+128..n0+255
        bool okb1 = (n0 + 128 + row) < N;
        long rB1 = okb1 ? (long)(n0 + 128 + row) * pB + k0 : 0;
#pragma unroll
        for (int j = 0; j < 4; j++) {
            int c = cbase + j;
            unsigned sw = SWZ((unsigned)(row * 128 + c * 16));
            cpa16(tb + SM_B0H + sw, Bbh + rB0 + c * 8, okb0);
            cpa16(tb + SM_B0L + sw, Bbl + rB0 + c * 8, okb0);
            cpa16(tb + SM_B1H + sw, Bbh + rB1 + c * 8, okb1);
            cpa16(tb + SM_B1L + sw, Bbl + rB1 + c * 8, okb1);
        }
    };

    // prologue: fill 2 stages
    issueLoads(0); cpa_commit();
    issueLoads(1); cpa_commit();

    for (int i = 0; i < nt; i++) {
        // committed groups here = i+2 (stages 0..i+1), except none after nt-1.
        if (i <= nt - 2) cpa_wait1();   // allow newest 1 pending -> stage i done
        else             cpa_wait0();
        __syncthreads();
        asm volatile("fence.proxy.async.shared::cta;" ::: "memory");
        if (tid == 0) {
            unsigned tb = tiles + (unsigned)(i & 1) * STAGE_BYTES;
            unsigned long long daH  = make_desc(tb);
            unsigned long long daL  = make_desc(tb + SM_A_L);
            unsigned long long db0H = make_desc(tb + SM_B0H);
            unsigned long long db0L = make_desc(tb + SM_B0L);
            unsigned long long db1H = make_desc(tb + SM_B1H);
            unsigned long long db1L = make_desc(tb + SM_B1L);
#pragma unroll
            for (int ks = 0; ks < 4; ks++) {
                unsigned en0 = (i == 0 && ks == 0) ? 0u : 1u;
                mma_ss_f16(tmem, daH + ks * 2, db0H + ks * 2, en0);
                mma_ss_f16(tmem, daL + ks * 2, db0H + ks * 2, 1u);
                mma_ss_f16(tmem, daH + ks * 2, db0L + ks * 2, 1u);
                if (act1) {
                    mma_ss_f16(tmem + 128, daH + ks * 2, db1H + ks * 2, en0);
                    mma_ss_f16(tmem + 128, daL + ks * 2, db1H + ks * 2, 1u);
                    mma_ss_f16(tmem + 128, daH + ks * 2, db1L + ks * 2, 1u);
                }
            }
            asm volatile(
                "tcgen05.commit.cta_group::1.mbarrier::arrive::one.shared::cluster.b64 [%0];"
                :: "r"(mbb + 8u * (i & 1)) : "memory");
        }
        // recycle buffer i%2 for stage i+2: needs MMA(i) done.
        // fill(i+1) already in flight overlaps this drain.
        if (i + 2 < nt) {
            mbar_wait(mbb + 8u * (i & 1), (i >> 1) & 1);
            issueLoads(i + 2);
            cpa_commit();
        }
    }
    // drain: stages nt-2 and nt-1 not yet waited (recycle covered <= nt-3)
    if (nt >= 2) mbar_wait(mbb + 8u * ((nt - 2) & 1), ((nt - 2) >> 1) & 1);
    mbar_wait(mbb + 8u * ((nt - 1) & 1), ((nt - 1) >> 1) & 1);
    asm volatile("tcgen05.fence::after_thread_sync;" ::: "memory");

    if (wid < 4) {
        int r = m0 + wid * 32 + lane;
        // 8 groups of 32 columns (acc0: 0..127, acc1: 128..255)
#pragma unroll
        for (int gc = 0; gc < 8; gc++) {
            int nb = n0 + gc * 32;
            if (nb >= N) break;
            unsigned q[32];
            ldtm32(q, tmem + gc * 32);
            asm volatile("tcgen05.wait::ld.sync.aligned;" ::: "memory");
            if (EPI == 0 && cCol == 1) {
                float* crow = C + coff + (long)r * cRow;
#pragma unroll
                for (int c = 0; c < 32; c += 4) {
                    int n = nb + c;
                    if (n >= N) break;
                    float4 v;
                    v.x = __uint_as_float(q[c + 0]) * alpha;
                    v.y = __uint_as_float(q[c + 1]) * alpha;
                    v.z = __uint_as_float(q[c + 2]) * alpha;
                    v.w = __uint_as_float(q[c + 3]) * alpha;
                    if (bias_e) {
                        v.x += __ldg(bias_e + n);     v.y += __ldg(bias_e + n + 1);
                        v.z += __ldg(bias_e + n + 2); v.w += __ldg(bias_e + n + 3);
                    }
                    if (relu) {
                        v.x = fmaxf(v.x, 0.f); v.y = fmaxf(v.y, 0.f);
                        v.z = fmaxf(v.z, 0.f); v.w = fmaxf(v.w, 0.f);
                    }
                    *(float4*)(crow + n) = v;
                }
            } else {
#pragma unroll
                for (int c = 0; c < 32; c += 2) {
                    int n = nb + c;
                    if (n >= N) break;
                    float v0 = __uint_as_float(q[c])     * alpha;
                    float v1 = __uint_as_float(q[c + 1]) * alpha;
                    if (bias_e) { v0 += __ldg(bias_e + n); v1 += __ldg(bias_e + n + 1); }
                    if (relu) { v0 = fmaxf(v0, 0.f); v1 = fmaxf(v1, 0.f); }
                    if (EPI == 0) {
                        C[coff + (long)r * cRow + (long)n * cCol]       = v0;
                        C[coff + (long)r * cRow + (long)(n + 1) * cCol] = v1;
                    } else if (EPI == 1) {
                        bf162 hv = __floats2bfloat162_rn(v0, v1);
                        bf162 lv = __floats2bfloat162_rn(
                            v0 - __bfloat162float(hv.x), v1 - __bfloat162float(hv.y));
                        *(bf162*)&Sh[coff + (long)r * sPitch + n] = hv;
                        *(bf162*)&Sl[coff + (long)r * sPitch + n] = lv;
                    } else {
                        bf16 h0, l0, h1, l1;
                        fsplit(v0, h0, l0); fsplit(v1, h1, l1);
                        Sh[coff + (long)n * sPitch + r] = h0;
                        Sl[coff + (long)n * sPitch + r] = l0;
                        Sh[coff + (long)(n + 1) * sPitch + r] = h1;
                        Sl[coff + (long)(n + 1) * sPitch + r] = l1;
                    }
                }
            }
        }
        asm volatile("tcgen05.fence::before_thread_sync;" ::: "memory");
    }

    __syncthreads();
    if (tid == 0) {
#pragma unroll
        for (int j = 0; j < 2; j++)
            asm volatile("mbarrier.inval.shared.b64 [%0];"
                         :: "r"(mbb + 8u * j) : "memory");
    }
    if (wid == 0)
        asm volatile("tcgen05.dealloc.cta_group::1.sync.aligned.b32 %0, %1;"
                     :: "r"(tmem), "r"(256u));

#else
    // ========= mma.sync fallback (plain sm_103): four 64-col halves =========
    unsigned* AsH = smw;
    unsigned* AsL = smw + A_WORDS;
    unsigned* BsH = smw + 2*A_WORDS;
    unsigned* BsL = smw + 2*A_WORDS + B_WORDS;

    int wm0 = (wid & 3) * 32, wn0 = (wid >> 2) * 32;
    int grp = lane >> 2, qid = lane & 3;

    unsigned aH_s = (unsigned)__cvta_generic_to_shared(AsH);
    unsigned aL_s = (unsigned)__cvta_generic_to_shared(AsL);
    unsigned bH_s = (unsigned)__cvta_generic_to_shared(BsH);
    unsigned bL_s = (unsigned)__cvta_generic_to_shared(BsL);
    unsigned a_off = (unsigned)((lane & 15) * SKP + (lane >> 4) * 4) * 4u;
    unsigned b_off = (unsigned)(((lane & 7) + (lane >> 4) * 8) * SKP +
                                ((lane >> 3) & 1) * 4) * 4u;

    int arow = tid >> 1, acol = (tid & 1) * 2;
    int brow = tid >> 2, bchk = tid & 3;

    for (int half = 0; half < 4; half++) {
        int n0h = n0 + half * 64;
        if (n0h >= N) break;

        auto issueLoads = [&](int k0, int buf) {
            unsigned aw = (unsigned)(buf * ABUF);
            unsigned bw = (unsigned)(buf * BBUF);
            long rbase; bool ok = true;
            if (CONV) {
                int kw = k0 / pA;
                int co = k0 - kw * pA;
                int tp = m0 + arow - 1 + kw;
                ok = (tp >= 0 && tp < M);
                rbase = ok ? (long)tp * pA + co : 0;
            } else {
                rbase = (long)(m0 + arow) * pA + k0;
            }
#pragma unroll
            for (int c = 0; c < 2; c++) {
                long o = rbase + (acol + c) * 8;
                unsigned d = (aw + (unsigned)(arow * SKP + (acol + c) * 4)) * 4u;
                cpa16(aH_s + d, Abh + o, ok);
                cpa16(aL_s + d, Abl + o, ok);
            }
            bool okb = (n0h + brow) < N;
            long ob = okb ? (long)(n0h + brow) * pB + k0 + bchk * 8 : 0;
            unsigned db = (bw + (unsigned)(brow * SKP + bchk * 4)) * 4u;
            cpa16(bH_s + db, Bbh + ob, okb);
            cpa16(bL_s + db, Bbl + ob, okb);
        };

        float acc[2][4][4];
#pragma unroll
        for (int mt = 0; mt < 2; mt++)
#pragma unroll
            for (int ntt = 0; ntt < 4; ntt++)
#pragma unroll
                for (int i = 0; i < 4; i++) acc[mt][ntt][i] = 0.f;

        issueLoads(0, 0);
        cpa_commit();
        cpa_wait0();
        __syncthreads();

        int buf = 0;
        for (int k0 = 0; k0 < Kd; k0 += 32) {
            if (k0 + 32 < Kd) issueLoads(k0 + 32, buf ^ 1);
            cpa_commit();

            unsigned abuf_b = (unsigned)(buf * ABUF) * 4u;
            unsigned bbuf_b = (unsigned)(buf * BBUF) * 4u;
#pragma unroll
            for (int kk = 0; kk < 2; kk++) {
                unsigned ko_b = (unsigned)(kk * 8) * 4u;
                unsigned aH[2][4], aL[2][4], bH[4][2], bL[4][2];
#pragma unroll
                for (int mt = 0; mt < 2; mt++) {
                    unsigned row_b = (unsigned)((wm0 + mt * 16) * SKP) * 4u;
                    ldsm_x4(aH[mt][0], aH[mt][1], aH[mt][2], aH[mt][3],
                            aH_s + abuf_b + row_b + a_off + ko_b);
                    ldsm_x4(aL[mt][0], aL[mt][1], aL[mt][2], aL[mt][3],
                            aL_s + abuf_b + row_b + a_off + ko_b);
                }
#pragma unroll
                for (int nh = 0; nh < 2; nh++) {
                    unsigned row_b = (unsigned)((wn0 + nh * 16) * SKP) * 4u;
                    ldsm_x4(bH[nh*2][0], bH[nh*2][1], bH[nh*2+1][0], bH[nh*2+1][1],
                            bH_s + bbuf_b + row_b + b_off + ko_b);
                    ldsm_x4(bL[nh*2][0], bL[nh*2][1], bL[nh*2+1][0], bL[nh*2+1][1],
                            bL_s + bbuf_b + row_b + b_off + ko_b);
                }
#pragma unroll
                for (int mt = 0; mt < 2; mt++)
#pragma unroll
                    for (int ntt = 0; ntt < 4; ntt++) {
                        mma_bf16(acc[mt][ntt], aH[mt][0], aH[mt][1], aH[mt][2], aH[mt][3],
                                 bH[ntt][0], bH[ntt][1]);
                        mma_bf16(acc[mt][ntt], aL[mt][0], aL[mt][1], aL[mt][2], aL[mt][3],
                                 bH[ntt][0], bH[ntt][1]);
                        mma_bf16(acc[mt][ntt], aH[mt][0], aH[mt][1], aH[mt][2], aH[mt][3],
                                 bL[ntt][0], bL[ntt][1]);
                    }
            }
            cpa_wait0();
            __syncthreads();
            buf ^= 1;
        }

#pragma unroll
        for (int mt = 0; mt < 2; mt++) {
            int r0 = m0 + wm0 + mt * 16 + grp;
#pragma unroll
            for (int ntt = 0; ntt < 4; ntt++) {
                int n = n0h + wn0 + ntt * 8 + qid * 2;
                if (n >= N) continue;
#pragma unroll
                for (int half2 = 0; half2 < 2; half2++) {
                    int r = r0 + half2 * 8;
                    float v0 = acc[mt][ntt][half2 * 2 + 0] * alpha;
                    float v1 = acc[mt][ntt][half2 * 2 + 1] * alpha;
                    if (bias_e) { v0 += bias_e[n]; v1 += bias_e[n + 1]; }
                    if (relu) { v0 = fmaxf(v0, 0.f); v1 = fmaxf(v1, 0.f); }
                    if (EPI == 0) {
                        C[coff + (long)r * cRow + (long)n * cCol]       = v0;
                        C[coff + (long)r * cRow + (long)(n + 1) * cCol] = v1;
                    } else if (EPI == 1) {
                        bf162 hv = __floats2bfloat162_rn(v0, v1);
                        bf162 lv = __floats2bfloat162_rn(
                            v0 - __bfloat162float(hv.x), v1 - __bfloat162float(hv.y));
                        *(bf162*)&Sh[coff + (long)r * sPitch + n] = hv;
                        *(bf162*)&Sl[coff + (long)r * sPitch + n] = lv;
                    } else {
                        bf16 h0, l0, h1, l1;
                        fsplit(v0, h0, l0); fsplit(v1, h1, l1);
                        Sh[coff + (long)n * sPitch + r] = h0;
                        Sl[coff + (long)n * sPitch + r] = l0;
                        Sh[coff + (long)(n + 1) * sPitch + r] = h1;
                        Sl[coff + (long)(n + 1) * sPitch + r] = l1;
                    }
                }
            }
        }
        __syncthreads();
    }
#endif
}

// ---------------- row softmax (fp32 in, split planes out) ----------------
__global__ void softmax_k(const float* __restrict__ s, bf16* __restrict__ sh,
                          bf16* __restrict__ sl, int T) {
    long r = blockIdx.x;
    const float* p = s + r * (long)T;
    int n = T >> 8;
    int tid = threadIdx.x;
    float v[4];
    float mx = -3.0e38f;
    for (int i = 0; i < n; i++) { v[i] = p[i * 256 + tid]; mx = fmaxf(mx, v[i]); }
    __shared__ float red[256];
    red[tid] = mx; __syncthreads();
    for (int st = 128; st > 0; st >>= 1) {
        if (tid < st) red[tid] = fmaxf(red[tid], red[tid + st]);
        __syncthreads();
    }
    mx = red[0]; __syncthreads();
    float sum = 0.f;
    for (int i = 0; i < n; i++) { v[i] = expf(v[i] - mx); sum += v[i]; }
    red[tid] = sum; __syncthreads();
    for (int st = 128; st > 0; st >>= 1) {
        if (tid < st) red[tid] += red[tid + st];
        __syncthreads();
    }
    float inv = 1.f / red[0];
    for (int i = 0; i < n; i++) {
        float val = v[i] * inv;
        bf16 h, l; fsplit(val, h, l);
        sh[r * (long)T + i * 256 + tid] = h;
        sl[r * (long)T + i * 256 + tid] = l;
    }
}

// ---------------- LayerNorm ----------------
__global__ void ln_k(const float* __restrict__ a, const float* __restrict__ b,
                     const float* __restrict__ sc, const float* __restrict__ bi,
                     float* __restrict__ o, bf16* __restrict__ sh,
                     bf16* __restrict__ sl) {
    int r = blockIdx.x;
    int tid = threadIdx.x;
    const float* ar = a + (long)r * HD;
    const float* br = b ? b + (long)r * HD : (const float*)0;
    float v[3];
    float s = 0.f;
#pragma unroll
    for (int i = 0; i < 3; i++) {
        int idx = tid + i * 128;
        v[i] = ar[idx] + (br ? br[idx] : 0.f);
        s += v[i];
    }
    __shared__ float red[128];
    red[tid] = s; __syncthreads();
    for (int st = 64; st > 0; st >>= 1) {
        if (tid < st) red[tid] += red[tid + st];
        __syncthreads();
    }
    float m = red[0] / (float)HD; __syncthreads();
    float sq = 0.f;
#pragma unroll
    for (int i = 0; i < 3; i++) { float d = v[i] - m; sq += d * d; }
    red[tid] = sq; __syncthreads();
    for (int st = 64; st > 0; st >>= 1) {
        if (tid < st) red[tid] += red[tid + st];
        __syncthreads();
    }
    float rs = rsqrtf(red[0] / (float)HD + 1e-5f);
    float* orow = o + (long)r * HD;
#pragma unroll
    for (int i = 0; i < 3; i++) {
        int idx = tid + i * 128;
        float val = (v[i] - m) * rs * sc[idx] + bi[idx];
        orow[idx] = val;
        if (sh) {
            bf16 h, l; fsplit(val, h, l);
            sh[(long)r * HD + idx] = h;
            sl[(long)r * HD + idx] = l;
        }
    }
}

// ---------------- aligner final linear H -> 1 ----------------
__global__ void lin1_k(const float* __restrict__ h, const float* __restrict__ w,
                       const float* __restrict__ b, float* __restrict__ o) {
    int r = blockIdx.x;
    int tid = threadIdx.x;
    float s = 0.f;
#pragma unroll
    for (int i = 0; i < 3; i++) {
        int idx = tid + i * 128;
        s += h[(long)r * HD + idx] * w[idx];
    }
    __shared__ float red[128];
    red[tid] = s; __syncthreads();
    for (int st = 64; st > 0; st >>= 1) {
        if (tid < st) red[tid] += red[tid + st];
        __syncthreads();
    }
    if (tid == 0) o[r] = red[0] + b[0];
}

// ---------------- duration cumsum (int32/int64 agnostic) ----------------
__global__ void cum_k(const int* __restrict__ al32, int* __restrict__ cum) {
    __shared__ int is64;
    if (threadIdx.x == 0) {
        int odd_zero = 1;
        for (int i = 1; i < 512; i += 2)
            if (al32[i] != 0) { odd_zero = 0; break; }
        is64 = odd_zero;
    }
    __syncthreads();
    int b = threadIdx.x;
    if (b < NB) {
        int acc = 0;
        for (int s = 0; s < NS; s++) {
            int d = is64 ? al32[2 * (b * NS + s)] : al32[b * NS + s];
            acc += d;
            cum[b * NS + s] = acc;
        }
    }
}

// ---------------- length regulator gather + posenc ----------------
__global__ void expand_k(const float* __restrict__ x, const int* __restrict__ cum,
                         float* __restrict__ y, bf16* __restrict__ sh,
                         bf16* __restrict__ sl) {
    int bt = blockIdx.x;
    int b = bt / TOUT, t = bt % TOUT;
    const int* c = cum + b * NS;
    int lo = 0, hi = NS;
    while (lo < hi) { int mid = (lo + hi) >> 1; if (c[mid] <= t) lo = mid + 1; else hi = mid; }
    int idx = lo; if (idx > NS - 1) idx = NS - 1;
    bool valid = t < c[NS - 1];
    const float* xr = x + ((long)b * NS + idx) * HD;
    long base = ((long)b * TOUT + t) * HD;
    for (int i = threadIdx.x; i < HD; i += blockDim.x) {
        float v = valid ? xr[i] : 0.f;
        float val = v + pe_val(t, i);
        y[base + i] = val;
        bf16 h, l; fsplit(val, h, l);
        sh[base + i] = h; sl[base + i] = l;
    }
}

// ---------------- host orchestration ----------------
extern "C" void kernel_launch(void* const* d_in, const int* in_sizes, int n_in,
                              void* d_out, int out_size) {
    const int*   tokens     = (const int*)d_in[0];
    const int*   alignes32  = (const int*)d_in[1];
    const float* tok_emb    = (const float*)d_in[2];
    const float* enc_attn_w = (const float*)d_in[3];
    const float* enc_attn_b = (const float*)d_in[4];
    const float* enc_c1w    = (const float*)d_in[5];
    const float* enc_c1b    = (const float*)d_in[6];
    const float* enc_c2w    = (const float*)d_in[7];
    const float* enc_c2b    = (const float*)d_in[8];
    const float* enc_ln     = (const float*)d_in[9];
    const float* dec_attn_w = (const float*)d_in[10];
    const float* dec_attn_b = (const float*)d_in[11];
    const float* dec_c1w    = (const float*)d_in[12];
    const float* dec_c1b    = (const float*)d_in[13];
    const float* dec_c2w    = (const float*)d_in[14];
    const float* dec_c2b    = (const float*)d_in[15];
    const float* dec_ln     = (const float*)d_in[16];
    const float* al_c1w     = (const float*)d_in[17];
    const float* al_c1b     = (const float*)d_in[18];
    const float* al_c2w     = (const float*)d_in[19];
    const float* al_c2b     = (const float*)d_in[20];
    const float* al_ln      = (const float*)d_in[21];
    const float* al_lin_w   = (const float*)d_in[22];
    const float* al_lin_b   = (const float*)d_in[23];
    const float* dec_lin_w  = (const float*)d_in[24];
    const float* dec_lin_b  = (const float*)d_in[25];

    float* out     = (float*)d_out;
    float* out_len = out + (size_t)NB * MEL * TOUT;

    cudaFuncSetAttribute(gemm_bf<0,0>, cudaFuncAttributeMaxDynamicSharedMemorySize, SMEM_BYTES);
    cudaFuncSetAttribute(gemm_bf<0,1>, cudaFuncAttributeMaxDynamicSharedMemorySize, SMEM_BYTES);
    cudaFuncSetAttribute(gemm_bf<0,2>, cudaFuncAttributeMaxDynamicSharedMemorySize, SMEM_BYTES);
    cudaFuncSetAttribute(gemm_bf<1,0>, cudaFuncAttributeMaxDynamicSharedMemorySize, SMEM_BYTES);
    cudaFuncSetAttribute(gemm_bf<1,1>, cudaFuncAttributeMaxDynamicSharedMemorySize, SMEM_BYTES);

    void* p;
    float *gx, *gy, *gu, *gsf, *gha, *ghb; int* gcum;
    cudaGetSymbolAddress(&p, g_x);   gx   = (float*)p;
    cudaGetSymbolAddress(&p, g_y);   gy   = (float*)p;
    cudaGetSymbolAddress(&p, g_u);   gu   = (float*)p;
    cudaGetSymbolAddress(&p, g_sf);  gsf  = (float*)p;
    cudaGetSymbolAddress(&p, g_ha);  gha  = (float*)p;
    cudaGetSymbolAddress(&p, g_hb);  ghb  = (float*)p;
    cudaGetSymbolAddress(&p, g_cum); gcum = (int*)p;

    bf16 *wa_h, *wa_l, *w1_h, *w1_l, *w2_h, *w2_l, *wal_h, *wal_l, *wm_h, *wm_l;
    bf16 *xs_h, *xs_l, *qk_h, *qk_l, *vs_h, *vs_l, *ss_h, *ss_l, *ts_h, *ts_l, *hs_h, *hs_l;
    cudaGetSymbolAddress(&p, g_wa_h);  wa_h  = (bf16*)p;
    cudaGetSymbolAddress(&p, g_wa_l);  wa_l  = (bf16*)p;
    cudaGetSymbolAddress(&p, g_w1_h);  w1_h  = (bf16*)p;
    cudaGetSymbolAddress(&p, g_w1_l);  w1_l  = (bf16*)p;
    cudaGetSymbolAddress(&p, g_w2_h);  w2_h  = (bf16*)p;
    cudaGetSymbolAddress(&p, g_w2_l);  w2_l  = (bf16*)p;
    cudaGetSymbolAddress(&p, g_wal_h); wal_h = (bf16*)p;
    cudaGetSymbolAddress(&p, g_wal_l); wal_l = (bf16*)p;
    cudaGetSymbolAddress(&p, g_wm_h);  wm_h  = (bf16*)p;
    cudaGetSymbolAddress(&p, g_wm_l);  wm_l  = (bf16*)p;
    cudaGetSymbolAddress(&p, g_xs_h);  xs_h  = (bf16*)p;
    cudaGetSymbolAddress(&p, g_xs_l);  xs_l  = (bf16*)p;
    cudaGetSymbolAddress(&p, g_qk_h);  qk_h  = (bf16*)p;
    cudaGetSymbolAddress(&p, g_qk_l);  qk_l  = (bf16*)p;
    cudaGetSymbolAddress(&p, g_vs_h);  vs_h  = (bf16*)p;
    cudaGetSymbolAddress(&p, g_vs_l);  vs_l  = (bf16*)p;
    cudaGetSymbolAddress(&p, g_ss_h);  ss_h  = (bf16*)p;
    cudaGetSymbolAddress(&p, g_ss_l);  ss_l  = (bf16*)p;
    cudaGetSymbolAddress(&p, g_ts_h);  ts_h  = (bf16*)p;
    cudaGetSymbolAddress(&p, g_ts_l);  ts_l  = (bf16*)p;
    cudaGetSymbolAddress(&p, g_hs_h);  hs_h  = (bf16*)p;
    cudaGetSymbolAddress(&p, g_hs_l);  hs_l  = (bf16*)p;

    const float scl = 1.f / sqrtf((float)DH);
    const float* NOB = (const float*)0;
    float* NOC = (float*)0;
    bf16* NOS = (bf16*)0;
    dim3 tb(32, 8);

    // ---- weight transpose + split pre-passes ----
    tsplit_k<<<dim3(12, 12, 16), tb>>>(enc_attn_w, wa_h, wa_l, HD, HD);
    tsplit_k<<<dim3(12, 12, 16), tb>>>(dec_attn_w, wa_h + 16L*HD*HD, wa_l + 16L*HD*HD, HD, HD);
    tsplit_k<<<dim3(48, 36, 4), tb>>>(enc_c1w, w1_h, w1_l, KW*HD, HD2);
    tsplit_k<<<dim3(48, 36, 4), tb>>>(dec_c1w, w1_h + 4L*HD2*KW*HD, w1_l + 4L*HD2*KW*HD, KW*HD, HD2);
    tsplit_k<<<dim3(12, 144, 4), tb>>>(enc_c2w, w2_h, w2_l, KW*HD2, HD);
    tsplit_k<<<dim3(12, 144, 4), tb>>>(dec_c2w, w2_h + 4L*HD*KW*HD2, w2_l + 4L*HD*KW*HD2, KW*HD2, HD);
    tsplit_k<<<dim3(12, 36, 1), tb>>>(al_c1w, wal_h, wal_l, KW*HD, HD);
    tsplit_k<<<dim3(12, 36, 1), tb>>>(al_c2w, wal_h + (long)HD*KW*HD, wal_l + (long)HD*KW*HD, KW*HD, HD);
    tsplit_k<<<dim3(3, 12, 1), tb>>>(dec_lin_w, wm_h, wm_l, HD, MEL);

    embed_k<<<NB * NS, 128>>>(tokens, tok_emb, gx, xs_h, xs_l);

    auto fft_block = [&](float* xf, int T, int lidx, const float* ab,
                         const float* c1b, const float* c2b, const float* lnp) {
        long TH = (long)T * HD;
        const bf16* wah = wa_h + (long)lidx * 4 * HD * HD;
        const bf16* wal = wa_l + (long)lidx * 4 * HD * HD;
        // q,k projections -> split planes (z = 2*NB), N=384 -> 2 x-tiles
        gemm_bf<0,1><<<dim3(2, T/128, 2*NB), 256, SMEM_BYTES>>>(
            xs_h, xs_l, NB, 0, TH, HD,
            wah, wal, (long)HD*HD, 0, HD,
            ab, HD,
            NOC, (long)NB*TH, TH, 0, 0,
            qk_h, qk_l, HD, T, HD, HD, 1.f, 0);
        // v projection -> transposed split planes [b][hd][t]
        gemm_bf<0,2><<<dim3(2, T/128, NB), 256, SMEM_BYTES>>>(
            xs_h, xs_l, NB, 0, TH, HD,
            wah + 2L*HD*HD, wal + 2L*HD*HD, 0, 0, HD,
            ab + 2*HD, 0,
            NOC, 0, (long)HD*T, 0, 0,
            vs_h, vs_l, T, T, HD, HD, 1.f, 0);
        // scores = q @ k^T * scl  (fp32 out), N=T
        gemm_bf<0,0><<<dim3((T + 255)/256, T/128, NB*NHEAD), 256, SMEM_BYTES>>>(
            qk_h, qk_l, NHEAD, TH, DH, HD,
            qk_h + (long)NB*TH, qk_l + (long)NB*TH, TH, DH, HD,
            NOB, 0,
            gsf, (long)NHEAD*T*T, (long)T*T, T, 1,
            NOS, NOS, 0, T, T, DH, scl, 0);
        softmax_k<<<NB * NHEAD * T, 256>>>(gsf, ss_h, ss_l, T);
        // attn @ V -> split planes gt  (N = DH = 192 -> 1 x-tile)
        gemm_bf<0,1><<<dim3(1, T/128, NB*NHEAD), 256, SMEM_BYTES>>>(
            ss_h, ss_l, NHEAD, (long)NHEAD*T*T, (long)T*T, T,
            vs_h, vs_l, (long)HD*T, (long)DH*T, T,
            NOB, 0,
            NOC, TH, DH, 0, 0,
            ts_h, ts_l, HD, T, DH, T, 1.f, 0);
        // output projection -> fp32 gu, N=384 -> 2 x-tiles
        gemm_bf<0,0><<<dim3(2, T/128, NB), 256, SMEM_BYTES>>>(
            ts_h, ts_l, NB, 0, TH, HD,
            wah + 3L*HD*HD, wal + 3L*HD*HD, 0, 0, HD,
            ab + 3*HD, 0,
            gu, 0, TH, HD, 1,
            NOS, NOS, 0, T, HD, HD, 1.f, 0);
        ln_k<<<NB * T, 128>>>(xf, gu, lnp + 0, lnp + HD, xf, xs_h, xs_l);
        // conv1 -> relu -> split planes gh, N=1536 -> 6 x-tiles
        gemm_bf<1,1><<<dim3(6, T/128, NB), 256, SMEM_BYTES>>>(
            xs_h, xs_l, NB, 0, TH, HD,
            w1_h + (long)lidx*HD2*KW*HD, w1_l + (long)lidx*HD2*KW*HD, 0, 0, KW*HD,
            c1b, 0,
            NOC, 0, (long)T*HD2, 0, 0,
            hs_h, hs_l, HD2, T, HD2, KW*HD, 1.f, 1);
        // conv2 -> fp32 gu, N=384 -> 2 x-tiles
        gemm_bf<1,0><<<dim3(2, T/128, NB), 256, SMEM_BYTES>>>(
            hs_h, hs_l, NB, 0, (long)T*HD2, HD2,
            w2_h + (long)lidx*HD*KW*HD2, w2_l + (long)lidx*HD*KW*HD2, 0, 0, KW*HD2,
            c2b, 0,
            gu, 0, TH, HD, 1,
            NOS, NOS, 0, T, HD, KW*HD2, 1.f, 0);
        ln_k<<<NB * T, 128>>>(xf, gu, lnp + 2*HD, lnp + 3*HD, xf, xs_h, xs_l);
    };

    // ---- encoder ----
    for (int l = 0; l < NLAY; l++)
        fft_block(gx, NS, l, enc_attn_b + (long)l*4*HD,
                  enc_c1b + (long)l*HD2, enc_c2b + (long)l*HD,
                  enc_ln + (long)l*4*HD);

    // ---- aligner ----
    {
        long TH = (long)NS * HD;
        gemm_bf<1,0><<<dim3(2, NS/128, NB), 256, SMEM_BYTES>>>(
            xs_h, xs_l, NB, 0, TH, HD,
            wal_h, wal_l, 0, 0, KW*HD,
            al_c1b, 0,
            gha, 0, TH, HD, 1,
            NOS, NOS, 0, NS, HD, KW*HD, 1.f, 1);
        ln_k<<<NB * NS, 128>>>(gha, NOB, al_ln + 0, al_ln + HD, gha, ts_h, ts_l);
        gemm_bf<1,0><<<dim3(2, NS/128, NB), 256, SMEM_BYTES>>>(
            ts_h, ts_l, NB, 0, TH, HD,
            wal_h + (long)HD*KW*HD, wal_l + (long)HD*KW*HD, 0, 0, KW*HD,
            al_c2b, 0,
            ghb, 0, TH, HD, 1,
            NOS, NOS, 0, NS, HD, KW*HD, 1.f, 1);
        ln_k<<<NB * NS, 128>>>(ghb, NOB, al_ln + 2*HD, al_ln + 3*HD, ghb, NOS, NOS);
        lin1_k<<<NB * NS, 128>>>(ghb, al_lin_w, al_lin_b, out_len);
    }

    // ---- length regulator ----
    cum_k<<<1, NB>>>(alignes32, gcum);
    expand_k<<<NB * TOUT, 128>>>(gx, gcum, gy, xs_h, xs_l);

    // ---- decoder ----
    for (int l = 0; l < NLAY; l++)
        fft_block(gy, TOUT, NLAY + l, dec_attn_b + (long)l*4*HD,
                  dec_c1b + (long)l*HD2, dec_c2b + (long)l*HD,
                  dec_ln + (long)l*4*HD);

    // ---- mel projection: out[b][n][t] (transposed fp32 write), N=80 -> 1 tile ----
    gemm_bf<0,0><<<dim3(1, TOUT/128, NB), 256, SMEM_BYTES>>>(
        xs_h, xs_l, NB, 0, (long)TOUT*HD, HD,
        wm_h, wm_l, 0, 0, HD,
        dec_lin_b, 0,
        out, 0, (long)MEL*TOUT, 1, TOUT,
        NOS, NOS, 0, TOUT, MEL, HD, 1.f, 0);
}

// round 16
// speedup vs baseline: 1.2723x; 1.2723x over previous
#include <cuda_runtime.h>
#include <cuda_bf16.h>
#include <math.h>

// ---------------- problem constants ----------------
#define NB    16
#define NS    256
#define HD    384     // H
#define HD2   1536    // H2
#define NHEAD 2
#define DH    192     // H / NHEAD
#define KW    3
#define NLAY  4
#define TOUT  1024
#define MEL   80

typedef __nv_bfloat16  bf16;
typedef __nv_bfloat162 bf162;

// Is this device pass an sm_103a-specific (tcgen05-capable) compilation?
#if defined(__CUDA_ARCH__) && (defined(__CUDA_ARCH_FEAT_SM103_ALL) || \
    (defined(__CUDA_ARCH_SPECIFIC__) && (__CUDA_ARCH_SPECIFIC__ == 1030)))
#define TC5 1
#else
#define TC5 0
#endif

// ---------------- fp32 scratch ----------------
__device__ float g_x [NB*NS*HD];
__device__ float g_y [NB*TOUT*HD];
__device__ float g_u [NB*TOUT*HD];
__device__ float g_sf[NB*NHEAD*TOUT*TOUT];
__device__ float g_ha[NB*NS*HD];
__device__ float g_hb[NB*NS*HD];
__device__ int   g_cum[NB*NS];

// ---------------- bf16 hi/lo planes ----------------
#define DECL2(name, sz) \
    __device__ __align__(16) bf16 name##_h[sz]; \
    __device__ __align__(16) bf16 name##_l[sz]
DECL2(g_wa,  8*4*HD*HD);
DECL2(g_w1,  8*HD2*KW*HD);
DECL2(g_w2,  8*HD*KW*HD2);
DECL2(g_wal, 2*HD*KW*HD);
DECL2(g_wm,  MEL*HD);
DECL2(g_xs,  NB*TOUT*HD);
DECL2(g_qk,  2*NB*TOUT*HD);
DECL2(g_vs,  NB*HD*TOUT);
DECL2(g_ss,  NB*NHEAD*TOUT*TOUT);
DECL2(g_ts,  NB*TOUT*HD);
DECL2(g_hs,  NB*TOUT*HD2);

// ---------------- helpers ----------------
__device__ __forceinline__ void fsplit(float v, bf16& h, bf16& l) {
    h = __float2bfloat16(v);
    l = __float2bfloat16(v - __bfloat162float(h));
}

__device__ __forceinline__ float pe_val(int t, int h) {
    int i2 = (h >> 1) * 2;
    float den = expf(-9.210340371976184f * (float)i2 / (float)HD);
    float ang = (float)t * den;
    return (h & 1) ? cosf(ang) : sinf(ang);
}

__device__ __forceinline__ void cpa16(unsigned dst, const void* src, bool pred) {
    int sz = pred ? 16 : 0;                 // src-size 0 -> 16B zero-fill
    asm volatile("cp.async.cg.shared.global [%0], [%1], 16, %2;"
                 :: "r"(dst), "l"(src), "r"(sz));
}
__device__ __forceinline__ void cpa_commit() { asm volatile("cp.async.commit_group;"); }
__device__ __forceinline__ void cpa_wait0()  { asm volatile("cp.async.wait_group 0;"); }
__device__ __forceinline__ void cpa_wait1()  { asm volatile("cp.async.wait_group 1;"); }
__device__ __forceinline__ void cpa_wait2()  { asm volatile("cp.async.wait_group 2;"); }

// ---- mma.sync helpers (valid on plain sm_103) ----
__device__ __forceinline__ void mma_bf16(float* d, unsigned a0, unsigned a1,
                                         unsigned a2, unsigned a3,
                                         unsigned b0, unsigned b1) {
    asm volatile(
        "mma.sync.aligned.m16n8k16.row.col.f32.bf16.bf16.f32 "
        "{%0,%1,%2,%3},{%4,%5,%6,%7},{%8,%9},{%0,%1,%2,%3};"
        : "+f"(d[0]), "+f"(d[1]), "+f"(d[2]), "+f"(d[3])
        : "r"(a0), "r"(a1), "r"(a2), "r"(a3), "r"(b0), "r"(b1));
}
__device__ __forceinline__ void ldsm_x4(unsigned& r0, unsigned& r1, unsigned& r2,
                                        unsigned& r3, unsigned addr) {
    asm volatile("ldmatrix.sync.aligned.m8n8.x4.shared.b16 {%0,%1,%2,%3}, [%4];"
                 : "=r"(r0), "=r"(r1), "=r"(r2), "=r"(r3) : "r"(addr));
}

#if TC5
// ---- tcgen05 helpers (sm_103a-only pass) ----
__device__ __forceinline__ void mbar_wait(unsigned mbar, int parity) {
    asm volatile(
        "{\n\t.reg .pred P1;\n\t"
        "WL%=:\n\t"
        "mbarrier.try_wait.parity.acquire.cta.shared::cta.b64 P1, [%0], %1, 0x989680;\n\t"
        "@P1 bra.uni WD%=;\n\t"
        "bra.uni WL%=;\n\t"
        "WD%=:\n\t}"
        :: "r"(mbar), "r"(parity) : "memory");
}
// idesc: kind::f16, bf16 inputs, fp32 accum, M=128, N=128
#define IDESC_TC ((1u<<4)|(1u<<7)|(1u<<10)|((128u/8)<<17)|((128u/16)<<24))
__device__ __forceinline__ unsigned long long make_desc(unsigned addr) {
    const unsigned long long base =
        (2ULL << 61) | (1ULL << 46) | (64ULL << 32) | (1ULL << 16);  // SW128
    return base | ((unsigned long long)(addr >> 4) & 0x3FFFULL);
}
__device__ __forceinline__ void mma_ss_f16(unsigned dtmem, unsigned long long ad,
                                           unsigned long long bd, unsigned en) {
    asm volatile(
        "{\n\t.reg .pred p;\n\t"
        "setp.ne.u32 p, %5, 0;\n\t"
        "tcgen05.mma.cta_group::1.kind::f16 [%0], %1, %2, %3, {%4,%4,%4,%4}, p;\n\t}"
        :: "r"(dtmem), "l"(ad), "l"(bd), "r"(IDESC_TC), "r"(0u), "r"(en)
        : "memory");
}
__device__ __forceinline__ void ldtm32(unsigned* r, unsigned a) {
    asm volatile(
        "tcgen05.ld.sync.aligned.32x32b.x32.b32 "
        "{%0,%1,%2,%3,%4,%5,%6,%7,%8,%9,%10,%11,%12,%13,%14,%15,"
        "%16,%17,%18,%19,%20,%21,%22,%23,%24,%25,%26,%27,%28,%29,%30,%31}, [%32];"
        : "=r"(r[0]),  "=r"(r[1]),  "=r"(r[2]),  "=r"(r[3]),
          "=r"(r[4]),  "=r"(r[5]),  "=r"(r[6]),  "=r"(r[7]),
          "=r"(r[8]),  "=r"(r[9]),  "=r"(r[10]), "=r"(r[11]),
          "=r"(r[12]), "=r"(r[13]), "=r"(r[14]), "=r"(r[15]),
          "=r"(r[16]), "=r"(r[17]), "=r"(r[18]), "=r"(r[19]),
          "=r"(r[20]), "=r"(r[21]), "=r"(r[22]), "=r"(r[23]),
          "=r"(r[24]), "=r"(r[25]), "=r"(r[26]), "=r"(r[27]),
          "=r"(r[28]), "=r"(r[29]), "=r"(r[30]), "=r"(r[31])
        : "r"(a));
}
#define SWZ(o) ((o) ^ (((o) >> 3) & 0x70))
#endif  // TC5

// ---------------- weight transpose + split: in [K][N] fp32 -> planes [N][K] ----
__global__ void tsplit_k(const float* __restrict__ in, bf16* __restrict__ oh,
                         bf16* __restrict__ ol, int K, int N) {
    __shared__ float t[32][33];
    long stride = (long)K * N;
    const float* ib = in + blockIdx.z * stride;
    bf16* ohb = oh + blockIdx.z * stride;
    bf16* olb = ol + blockIdx.z * stride;
    int k0 = blockIdx.y * 32, n0 = blockIdx.x * 32;
    int tx = threadIdx.x, ty = threadIdx.y;
    for (int i = 0; i < 32; i += 8) {
        int k = k0 + ty + i, n = n0 + tx;
        t[ty + i][tx] = (k < K && n < N) ? ib[(long)k * N + n] : 0.f;
    }
    __syncthreads();
    for (int i = 0; i < 32; i += 8) {
        int n = n0 + ty + i, k = k0 + tx;
        if (n < N && k < K) {
            bf16 h, l; fsplit(t[tx][ty + i], h, l);
            ohb[(long)n * K + k] = h;
            olb[(long)n * K + k] = l;
        }
    }
}

// ---------------- embed + posenc ----------------
__global__ void embed_k(const int* __restrict__ tok, const float* __restrict__ emb,
                        float* __restrict__ x, bf16* __restrict__ sh,
                        bf16* __restrict__ sl) {
    int bt = blockIdx.x;
    int t  = bt % NS;
    int v  = tok[bt];
    const float* e = emb + (long)v * HD;
    long base = (long)bt * HD;
    for (int i = threadIdx.x; i < HD; i += blockDim.x) {
        float val = e[i] * 19.595917942265423f + pe_val(t, i);
        x[base + i] = val;
        bf16 h, l; fsplit(val, h, l);
        sh[base + i] = h; sl[base + i] = l;
    }
}

// ---------------- unified NT bf16 GEMM (3-term split) ----------------
// C = alpha * A @ B^T (+bias) (opt relu); A [m][k] planes pitch pA,
// B [n][k] planes pitch pB. batching: z=g; gq_=g/gdiv, gr_=g%gdiv.
// CONV=1: A row m -> time tp = m0+m-1+kw, kw = k0/pA.
// EPI: 0 = fp32 C, 1 = split planes [m][n], 2 = split planes transposed [n][m].
// Tiles: 128 x 128 (tcgen05, 3-stage pipe) / 128 x (2x64) (fallback).
// M%128==0, Kd%64==0 (and Kd>=192 for pipeline wait logic), N even.
#define SMEM_BYTES 198656
// mma.sync fallback layout
#define SKP 20
#define A_WORDS  (2*128*SKP)
#define B_WORDS  (2*64*SKP)
#define ABUF (128*SKP)
#define BBUF (64*SKP)
// tcgen05 layout: stage = A(2 planes x 16KB) + B(2 planes x 16KB) = 64KB, 3 stages
#define STAGE_BYTES 65536
#define SM_A_L 16384
#define SM_B_H 32768
#define SM_B_L 49152

template<int CONV, int EPI>
__global__ __launch_bounds__(256, 1) __cluster_dims__(1, 1, 1)
void gemm_bf(
    const bf16* __restrict__ Ah, const bf16* __restrict__ Al,
    int gdiv, long a1, long a2, int pA,
    const bf16* __restrict__ Bh, const bf16* __restrict__ Bl,
    long b1, long b2, int pB,
    const float* __restrict__ bias, long bstr,
    float* __restrict__ C, long c1, long c2, int cRow, int cCol,
    bf16* __restrict__ Sh, bf16* __restrict__ Sl, int sPitch,
    int M, int N, int Kd, float alpha, int relu)
{
    extern __shared__ unsigned smw[];

    int g = blockIdx.z;
    int gq_ = g / gdiv, gr_ = g % gdiv;
    const bf16* Abh = Ah + gq_ * a1 + gr_ * a2;
    const bf16* Abl = Al + gq_ * a1 + gr_ * a2;
    const bf16* Bbh = Bh + gq_ * b1 + gr_ * b2;
    const bf16* Bbl = Bl + gq_ * b1 + gr_ * b2;
    long coff = gq_ * c1 + gr_ * c2;
    const float* bias_e = bias ? bias + gq_ * bstr : (const float*)0;

    int m0 = blockIdx.y * 128, n0 = blockIdx.x * 128;
    int tid = threadIdx.x, lane = tid & 31, wid = tid >> 5;

#if TC5
    // ===== tcgen05 path (sm_103a): 128x128 tile, 3-stage pipeline =====
    unsigned sm0 = (unsigned)__cvta_generic_to_shared(smw);
    unsigned base = (sm0 + 1023u) & ~1023u;
    unsigned tptr = base;
    unsigned mbb  = base + 8;          // mb[j] = mbb + 8*j, j=0..2
    unsigned tiles = base + 1024;

    if (wid == 0) {
        asm volatile("tcgen05.alloc.cta_group::1.sync.aligned.shared::cta.b32 [%0], %1;"
                     :: "r"(tptr), "r"(128u) : "memory");
    }
    if (tid == 0) {
#pragma unroll
        for (int j = 0; j < 3; j++)
            asm volatile("mbarrier.init.shared.b64 [%0], %1;"
                         :: "r"(mbb + 8u * j), "r"(1u) : "memory");
    }
    __syncthreads();
    if (wid == 0)
        asm volatile("tcgen05.relinquish_alloc_permit.cta_group::1.sync.aligned;");
    unsigned tmem;
    asm volatile("ld.shared.b32 %0, [%1];" : "=r"(tmem) : "r"(tptr));

    int nt = Kd >> 6;   // >= 3 for all GEMMs in this network

    auto issueLoads = [&](int s) {            // stage s -> buffer s%3
        int k0 = s << 6;
        unsigned tb = tiles + (unsigned)(s % 3) * STAGE_BYTES;
        int row = tid >> 1;               // 0..127 (shared by A and B)
        int cbase = (tid & 1) * 4;        // 4 x 16B chunks per thread per plane
        // A
        long ra = 0; bool ok = true;
        if (CONV) {
            int kw = k0 / pA;
            int co = k0 - kw * pA;
            int tp = m0 + row - 1 + kw;
            ok = (tp >= 0 && tp < M);
            ra = ok ? (long)tp * pA + co : 0;
        } else {
            ra = (long)(m0 + row) * pA + k0;
        }
#pragma unroll
        for (int j = 0; j < 4; j++) {
            int c = cbase + j;
            unsigned d = tb + SWZ((unsigned)(row * 128 + c * 16));
            cpa16(d,          Abh + ra + c * 8, ok);
            cpa16(d + SM_A_L, Abl + ra + c * 8, ok);
        }
        // B: 128 rows
        bool okb = (n0 + row) < N;
        long rB = okb ? (long)(n0 + row) * pB + k0 : 0;
#pragma unroll
        for (int j = 0; j < 4; j++) {
            int c = cbase + j;
            unsigned d = tb + SM_B_H + SWZ((unsigned)(row * 128 + c * 16));
            cpa16(d,         Bbh + rB + c * 8, okb);
            cpa16(d + 16384, Bbl + rB + c * 8, okb);
        }
    };

    // prologue: fill 3 stages (nt >= 3 guaranteed)
    for (int j = 0; j < 3; j++) { issueLoads(j); cpa_commit(); }

    for (int i = 0; i < nt; i++) {
        // Exact group accounting: committed at this point = i+2 stages
        // (3 from prologue + one per iter 1..i-1), except no commits after
        // stage nt-1. Guarantee stage i complete:
        if (i == 0)            cpa_wait2();   // committed {0,1,2}, need 0
        else if (i == nt - 1)  cpa_wait0();   // need all
        else                   cpa_wait1();   // committed ..(i+1), need i
        __syncthreads();
        asm volatile("fence.proxy.async.shared::cta;" ::: "memory");
        if (tid == 0) {
            unsigned tb = tiles + (unsigned)(i % 3) * STAGE_BYTES;
            unsigned long long daH = make_desc(tb);
            unsigned long long daL = make_desc(tb + SM_A_L);
            unsigned long long dbH = make_desc(tb + SM_B_H);
            unsigned long long dbL = make_desc(tb + SM_B_L);
#pragma unroll
            for (int ks = 0; ks < 4; ks++) {
                unsigned en0 = (i == 0 && ks == 0) ? 0u : 1u;
                mma_ss_f16(tmem, daH + ks * 2, dbH + ks * 2, en0);
                mma_ss_f16(tmem, daL + ks * 2, dbH + ks * 2, 1u);
                mma_ss_f16(tmem, daH + ks * 2, dbL + ks * 2, 1u);
            }
            asm volatile(
                "tcgen05.commit.cta_group::1.mbarrier::arrive::one.shared::cluster.b64 [%0];"
                :: "r"(mbb + 8u * (i % 3)) : "memory");
        }
        // recycle buffer (i+2)%3 == (i-1)%3: needs MMA(i-1) done (committed
        // last iteration; its drain overlapped with this iteration's fill wait).
        if (i >= 1 && i + 2 < nt) {
            int s = i - 1;                          // stage whose MMA we await
            mbar_wait(mbb + 8u * (s % 3), (s / 3) & 1);
            issueLoads(i + 2);
            cpa_commit();
        }
    }
    // drain remaining MMA commits in stage order (keeps parity exact)
    for (int s = (nt >= 3 ? nt - 3 : 0); s < nt; s++)
        mbar_wait(mbb + 8u * (s % 3), (s / 3) & 1);
    asm volatile("tcgen05.fence::after_thread_sync;" ::: "memory");

    // ---- epilogue: all 8 warps; warp w (subpartition w&3) handles column
    //      groups {2*(w>>2), 2*(w>>2)+1} of its rows ----
    {
        int r = m0 + (wid & 3) * 32 + lane;
        int gc0 = (wid >> 2) * 2;
#pragma unroll
        for (int gi = 0; gi < 2; gi++) {
            int gc = gc0 + gi;
            int nb = n0 + gc * 32;
            if (nb >= N) break;
            unsigned q[32];
            ldtm32(q, tmem + gc * 32);
            asm volatile("tcgen05.wait::ld.sync.aligned;" ::: "memory");
            if (EPI == 0 && cCol == 1) {
                float* crow = C + coff + (long)r * cRow;
#pragma unroll
                for (int c = 0; c < 32; c += 4) {
                    int n = nb + c;
                    if (n >= N) break;
                    float4 v;
                    v.x = __uint_as_float(q[c + 0]) * alpha;
                    v.y = __uint_as_float(q[c + 1]) * alpha;
                    v.z = __uint_as_float(q[c + 2]) * alpha;
                    v.w = __uint_as_float(q[c + 3]) * alpha;
                    if (bias_e) {
                        v.x += __ldg(bias_e + n);     v.y += __ldg(bias_e + n + 1);
                        v.z += __ldg(bias_e + n + 2); v.w += __ldg(bias_e + n + 3);
                    }
                    if (relu) {
                        v.x = fmaxf(v.x, 0.f); v.y = fmaxf(v.y, 0.f);
                        v.z = fmaxf(v.z, 0.f); v.w = fmaxf(v.w, 0.f);
                    }
                    *(float4*)(crow + n) = v;
                }
            } else {
#pragma unroll
                for (int c = 0; c < 32; c += 2) {
                    int n = nb + c;
                    if (n >= N) break;
                    float v0 = __uint_as_float(q[c])     * alpha;
                    float v1 = __uint_as_float(q[c + 1]) * alpha;
                    if (bias_e) { v0 += __ldg(bias_e + n); v1 += __ldg(bias_e + n + 1); }
                    if (relu) { v0 = fmaxf(v0, 0.f); v1 = fmaxf(v1, 0.f); }
                    if (EPI == 0) {
                        C[coff + (long)r * cRow + (long)n * cCol]       = v0;
                        C[coff + (long)r * cRow + (long)(n + 1) * cCol] = v1;
                    } else if (EPI == 1) {
                        bf162 hv = __floats2bfloat162_rn(v0, v1);
                        bf162 lv = __floats2bfloat162_rn(
                            v0 - __bfloat162float(hv.x), v1 - __bfloat162float(hv.y));
                        *(bf162*)&Sh[coff + (long)r * sPitch + n] = hv;
                        *(bf162*)&Sl[coff + (long)r * sPitch + n] = lv;
                    } else {
                        bf16 h0, l0, h1, l1;
                        fsplit(v0, h0, l0); fsplit(v1, h1, l1);
                        Sh[coff + (long)n * sPitch + r] = h0;
                        Sl[coff + (long)n * sPitch + r] = l0;
                        Sh[coff + (long)(n + 1) * sPitch + r] = h1;
                        Sl[coff + (long)(n + 1) * sPitch + r] = l1;
                    }
                }
            }
        }
        asm volatile("tcgen05.fence::before_thread_sync;" ::: "memory");
    }

    __syncthreads();
    if (tid == 0) {
#pragma unroll
        for (int j = 0; j < 3; j++)
            asm volatile("mbarrier.inval.shared.b64 [%0];"
                         :: "r"(mbb + 8u * j) : "memory");
    }
    if (wid == 0)
        asm volatile("tcgen05.dealloc.cta_group::1.sync.aligned.b32 %0, %1;"
                     :: "r"(tmem), "r"(128u));

#else
    // ============ mma.sync fallback (plain sm_103): two 64-col halves ============
    unsigned* AsH = smw;
    unsigned* AsL = smw + A_WORDS;
    unsigned* BsH = smw + 2*A_WORDS;
    unsigned* BsL = smw + 2*A_WORDS + B_WORDS;

    int wm0 = (wid & 3) * 32, wn0 = (wid >> 2) * 32;
    int grp = lane >> 2, qid = lane & 3;

    unsigned aH_s = (unsigned)__cvta_generic_to_shared(AsH);
    unsigned aL_s = (unsigned)__cvta_generic_to_shared(AsL);
    unsigned bH_s = (unsigned)__cvta_generic_to_shared(BsH);
    unsigned bL_s = (unsigned)__cvta_generic_to_shared(BsL);
    unsigned a_off = (unsigned)((lane & 15) * SKP + (lane >> 4) * 4) * 4u;
    unsigned b_off = (unsigned)(((lane & 7) + (lane >> 4) * 8) * SKP +
                                ((lane >> 3) & 1) * 4) * 4u;

    int arow = tid >> 1, acol = (tid & 1) * 2;
    int brow = tid >> 2, bchk = tid & 3;

    for (int half = 0; half < 2; half++) {
        int n0h = n0 + half * 64;
        if (n0h >= N) break;

        auto issueLoads = [&](int k0, int buf) {
            unsigned aw = (unsigned)(buf * ABUF);
            unsigned bw = (unsigned)(buf * BBUF);
            long rbase; bool ok = true;
            if (CONV) {
                int kw = k0 / pA;
                int co = k0 - kw * pA;
                int tp = m0 + arow - 1 + kw;
                ok = (tp >= 0 && tp < M);
                rbase = ok ? (long)tp * pA + co : 0;
            } else {
                rbase = (long)(m0 + arow) * pA + k0;
            }
#pragma unroll
            for (int c = 0; c < 2; c++) {
                long o = rbase + (acol + c) * 8;
                unsigned d = (aw + (unsigned)(arow * SKP + (acol + c) * 4)) * 4u;
                cpa16(aH_s + d, Abh + o, ok);
                cpa16(aL_s + d, Abl + o, ok);
            }
            bool okb = (n0h + brow) < N;
            long ob = okb ? (long)(n0h + brow) * pB + k0 + bchk * 8 : 0;
            unsigned db = (bw + (unsigned)(brow * SKP + bchk * 4)) * 4u;
            cpa16(bH_s + db, Bbh + ob, okb);
            cpa16(bL_s + db, Bbl + ob, okb);
        };

        float acc[2][4][4];
#pragma unroll
        for (int mt = 0; mt < 2; mt++)
#pragma unroll
            for (int ntt = 0; ntt < 4; ntt++)
#pragma unroll
                for (int i = 0; i < 4; i++) acc[mt][ntt][i] = 0.f;

        issueLoads(0, 0);
        cpa_commit();
        cpa_wait0();
        __syncthreads();

        int buf = 0;
        for (int k0 = 0; k0 < Kd; k0 += 32) {
            if (k0 + 32 < Kd) issueLoads(k0 + 32, buf ^ 1);
            cpa_commit();

            unsigned abuf_b = (unsigned)(buf * ABUF) * 4u;
            unsigned bbuf_b = (unsigned)(buf * BBUF) * 4u;
#pragma unroll
            for (int kk = 0; kk < 2; kk++) {
                unsigned ko_b = (unsigned)(kk * 8) * 4u;
                unsigned aH[2][4], aL[2][4], bH[4][2], bL[4][2];
#pragma unroll
                for (int mt = 0; mt < 2; mt++) {
                    unsigned row_b = (unsigned)((wm0 + mt * 16) * SKP) * 4u;
                    ldsm_x4(aH[mt][0], aH[mt][1], aH[mt][2], aH[mt][3],
                            aH_s + abuf_b + row_b + a_off + ko_b);
                    ldsm_x4(aL[mt][0], aL[mt][1], aL[mt][2], aL[mt][3],
                            aL_s + abuf_b + row_b + a_off + ko_b);
                }
#pragma unroll
                for (int nh = 0; nh < 2; nh++) {
                    unsigned row_b = (unsigned)((wn0 + nh * 16) * SKP) * 4u;
                    ldsm_x4(bH[nh*2][0], bH[nh*2][1], bH[nh*2+1][0], bH[nh*2+1][1],
                            bH_s + bbuf_b + row_b + b_off + ko_b);
                    ldsm_x4(bL[nh*2][0], bL[nh*2][1], bL[nh*2+1][0], bL[nh*2+1][1],
                            bL_s + bbuf_b + row_b + b_off + ko_b);
                }
#pragma unroll
                for (int mt = 0; mt < 2; mt++)
#pragma unroll
                    for (int ntt = 0; ntt < 4; ntt++) {
                        mma_bf16(acc[mt][ntt], aH[mt][0], aH[mt][1], aH[mt][2], aH[mt][3],
                                 bH[ntt][0], bH[ntt][1]);
                        mma_bf16(acc[mt][ntt], aL[mt][0], aL[mt][1], aL[mt][2], aL[mt][3],
                                 bH[ntt][0], bH[ntt][1]);
                        mma_bf16(acc[mt][ntt], aH[mt][0], aH[mt][1], aH[mt][2], aH[mt][3],
                                 bL[ntt][0], bL[ntt][1]);
                    }
            }
            cpa_wait0();
            __syncthreads();
            buf ^= 1;
        }

#pragma unroll
        for (int mt = 0; mt < 2; mt++) {
            int r0 = m0 + wm0 + mt * 16 + grp;
#pragma unroll
            for (int ntt = 0; ntt < 4; ntt++) {
                int n = n0h + wn0 + ntt * 8 + qid * 2;
                if (n >= N) continue;
#pragma unroll
                for (int half2 = 0; half2 < 2; half2++) {
                    int r = r0 + half2 * 8;
                    float v0 = acc[mt][ntt][half2 * 2 + 0] * alpha;
                    float v1 = acc[mt][ntt][half2 * 2 + 1] * alpha;
                    if (bias_e) { v0 += bias_e[n]; v1 += bias_e[n + 1]; }
                    if (relu) { v0 = fmaxf(v0, 0.f); v1 = fmaxf(v1, 0.f); }
                    if (EPI == 0) {
                        C[coff + (long)r * cRow + (long)n * cCol]       = v0;
                        C[coff + (long)r * cRow + (long)(n + 1) * cCol] = v1;
                    } else if (EPI == 1) {
                        bf162 hv = __floats2bfloat162_rn(v0, v1);
                        bf162 lv = __floats2bfloat162_rn(
                            v0 - __bfloat162float(hv.x), v1 - __bfloat162float(hv.y));
                        *(bf162*)&Sh[coff + (long)r * sPitch + n] = hv;
                        *(bf162*)&Sl[coff + (long)r * sPitch + n] = lv;
                    } else {
                        bf16 h0, l0, h1, l1;
                        fsplit(v0, h0, l0); fsplit(v1, h1, l1);
                        Sh[coff + (long)n * sPitch + r] = h0;
                        Sl[coff + (long)n * sPitch + r] = l0;
                        Sh[coff + (long)(n + 1) * sPitch + r] = h1;
                        Sl[coff + (long)(n + 1) * sPitch + r] = l1;
                    }
                }
            }
        }
        __syncthreads();
    }
#endif
}

// ---------------- row softmax (fp32 in, split planes out) ----------------
__global__ void softmax_k(const float* __restrict__ s, bf16* __restrict__ sh,
                          bf16* __restrict__ sl, int T) {
    long r = blockIdx.x;
    const float* p = s + r * (long)T;
    int n = T >> 8;
    int tid = threadIdx.x;
    float v[4];
    float mx = -3.0e38f;
    for (int i = 0; i < n; i++) { v[i] = p[i * 256 + tid]; mx = fmaxf(mx, v[i]); }
    __shared__ float red[256];
    red[tid] = mx; __syncthreads();
    for (int st = 128; st > 0; st >>= 1) {
        if (tid < st) red[tid] = fmaxf(red[tid], red[tid + st]);
        __syncthreads();
    }
    mx = red[0]; __syncthreads();
    float sum = 0.f;
    for (int i = 0; i < n; i++) { v[i] = expf(v[i] - mx); sum += v[i]; }
    red[tid] = sum; __syncthreads();
    for (int st = 128; st > 0; st >>= 1) {
        if (tid < st) red[tid] += red[tid + st];
        __syncthreads();
    }
    float inv = 1.f / red[0];
    for (int i = 0; i < n; i++) {
        float val = v[i] * inv;
        bf16 h, l; fsplit(val, h, l);
        sh[r * (long)T + i * 256 + tid] = h;
        sl[r * (long)T + i * 256 + tid] = l;
    }
}

// ---------------- LayerNorm ----------------
__global__ void ln_k(const float* __restrict__ a, const float* __restrict__ b,
                     const float* __restrict__ sc, const float* __restrict__ bi,
                     float* __restrict__ o, bf16* __restrict__ sh,
                     bf16* __restrict__ sl) {
    int r = blockIdx.x;
    int tid = threadIdx.x;
    const float* ar = a + (long)r * HD;
    const float* br = b ? b + (long)r * HD : (const float*)0;
    float v[3];
    float s = 0.f;
#pragma unroll
    for (int i = 0; i < 3; i++) {
        int idx = tid + i * 128;
        v[i] = ar[idx] + (br ? br[idx] : 0.f);
        s += v[i];
    }
    __shared__ float red[128];
    red[tid] = s; __syncthreads();
    for (int st = 64; st > 0; st >>= 1) {
        if (tid < st) red[tid] += red[tid + st];
        __syncthreads();
    }
    float m = red[0] / (float)HD; __syncthreads();
    float sq = 0.f;
#pragma unroll
    for (int i = 0; i < 3; i++) { float d = v[i] - m; sq += d * d; }
    red[tid] = sq; __syncthreads();
    for (int st = 64; st > 0; st >>= 1) {
        if (tid < st) red[tid] += red[tid + st];
        __syncthreads();
    }
    float rs = rsqrtf(red[0] / (float)HD + 1e-5f);
    float* orow = o + (long)r * HD;
#pragma unroll
    for (int i = 0; i < 3; i++) {
        int idx = tid + i * 128;
        float val = (v[i] - m) * rs * sc[idx] + bi[idx];
        orow[idx] = val;
        if (sh) {
            bf16 h, l; fsplit(val, h, l);
            sh[(long)r * HD + idx] = h;
            sl[(long)r * HD + idx] = l;
        }
    }
}

// ---------------- aligner final linear H -> 1 ----------------
__global__ void lin1_k(const float* __restrict__ h, const float* __restrict__ w,
                       const float* __restrict__ b, float* __restrict__ o) {
    int r = blockIdx.x;
    int tid = threadIdx.x;
    float s = 0.f;
#pragma unroll
    for (int i = 0; i < 3; i++) {
        int idx = tid + i * 128;
        s += h[(long)r * HD + idx] * w[idx];
    }
    __shared__ float red[128];
    red[tid] = s; __syncthreads();
    for (int st = 64; st > 0; st >>= 1) {
        if (tid < st) red[tid] += red[tid + st];
        __syncthreads();
    }
    if (tid == 0) o[r] = red[0] + b[0];
}

// ---------------- duration cumsum (int32/int64 agnostic) ----------------
__global__ void cum_k(const int* __restrict__ al32, int* __restrict__ cum) {
    __shared__ int is64;
    if (threadIdx.x == 0) {
        int odd_zero = 1;
        for (int i = 1; i < 512; i += 2)
            if (al32[i] != 0) { odd_zero = 0; break; }
        is64 = odd_zero;
    }
    __syncthreads();
    int b = threadIdx.x;
    if (b < NB) {
        int acc = 0;
        for (int s = 0; s < NS; s++) {
            int d = is64 ? al32[2 * (b * NS + s)] : al32[b * NS + s];
            acc += d;
            cum[b * NS + s] = acc;
        }
    }
}

// ---------------- length regulator gather + posenc ----------------
__global__ void expand_k(const float* __restrict__ x, const int* __restrict__ cum,
                         float* __restrict__ y, bf16* __restrict__ sh,
                         bf16* __restrict__ sl) {
    int bt = blockIdx.x;
    int b = bt / TOUT, t = bt % TOUT;
    const int* c = cum + b * NS;
    int lo = 0, hi = NS;
    while (lo < hi) { int mid = (lo + hi) >> 1; if (c[mid] <= t) lo = mid + 1; else hi = mid; }
    int idx = lo; if (idx > NS - 1) idx = NS - 1;
    bool valid = t < c[NS - 1];
    const float* xr = x + ((long)b * NS + idx) * HD;
    long base = ((long)b * TOUT + t) * HD;
    for (int i = threadIdx.x; i < HD; i += blockDim.x) {
        float v = valid ? xr[i] : 0.f;
        float val = v + pe_val(t, i);
        y[base + i] = val;
        bf16 h, l; fsplit(val, h, l);
        sh[base + i] = h; sl[base + i] = l;
    }
}

// ---------------- host orchestration ----------------
extern "C" void kernel_launch(void* const* d_in, const int* in_sizes, int n_in,
                              void* d_out, int out_size) {
    const int*   tokens     = (const int*)d_in[0];
    const int*   alignes32  = (const int*)d_in[1];
    const float* tok_emb    = (const float*)d_in[2];
    const float* enc_attn_w = (const float*)d_in[3];
    const float* enc_attn_b = (const float*)d_in[4];
    const float* enc_c1w    = (const float*)d_in[5];
    const float* enc_c1b    = (const float*)d_in[6];
    const float* enc_c2w    = (const float*)d_in[7];
    const float* enc_c2b    = (const float*)d_in[8];
    const float* enc_ln     = (const float*)d_in[9];
    const float* dec_attn_w = (const float*)d_in[10];
    const float* dec_attn_b = (const float*)d_in[11];
    const float* dec_c1w    = (const float*)d_in[12];
    const float* dec_c1b    = (const float*)d_in[13];
    const float* dec_c2w    = (const float*)d_in[14];
    const float* dec_c2b    = (const float*)d_in[15];
    const float* dec_ln     = (const float*)d_in[16];
    const float* al_c1w     = (const float*)d_in[17];
    const float* al_c1b     = (const float*)d_in[18];
    const float* al_c2w     = (const float*)d_in[19];
    const float* al_c2b     = (const float*)d_in[20];
    const float* al_ln      = (const float*)d_in[21];
    const float* al_lin_w   = (const float*)d_in[22];
    const float* al_lin_b   = (const float*)d_in[23];
    const float* dec_lin_w  = (const float*)d_in[24];
    const float* dec_lin_b  = (const float*)d_in[25];

    float* out     = (float*)d_out;
    float* out_len = out + (size_t)NB * MEL * TOUT;

    cudaFuncSetAttribute(gemm_bf<0,0>, cudaFuncAttributeMaxDynamicSharedMemorySize, SMEM_BYTES);
    cudaFuncSetAttribute(gemm_bf<0,1>, cudaFuncAttributeMaxDynamicSharedMemorySize, SMEM_BYTES);
    cudaFuncSetAttribute(gemm_bf<0,2>, cudaFuncAttributeMaxDynamicSharedMemorySize, SMEM_BYTES);
    cudaFuncSetAttribute(gemm_bf<1,0>, cudaFuncAttributeMaxDynamicSharedMemorySize, SMEM_BYTES);
    cudaFuncSetAttribute(gemm_bf<1,1>, cudaFuncAttributeMaxDynamicSharedMemorySize, SMEM_BYTES);

    void* p;
    float *gx, *gy, *gu, *gsf, *gha, *ghb; int* gcum;
    cudaGetSymbolAddress(&p, g_x);   gx   = (float*)p;
    cudaGetSymbolAddress(&p, g_y);   gy   = (float*)p;
    cudaGetSymbolAddress(&p, g_u);   gu   = (float*)p;
    cudaGetSymbolAddress(&p, g_sf);  gsf  = (float*)p;
    cudaGetSymbolAddress(&p, g_ha);  gha  = (float*)p;
    cudaGetSymbolAddress(&p, g_hb);  ghb  = (float*)p;
    cudaGetSymbolAddress(&p, g_cum); gcum = (int*)p;

    bf16 *wa_h, *wa_l, *w1_h, *w1_l, *w2_h, *w2_l, *wal_h, *wal_l, *wm_h, *wm_l;
    bf16 *xs_h, *xs_l, *qk_h, *qk_l, *vs_h, *vs_l, *ss_h, *ss_l, *ts_h, *ts_l, *hs_h, *hs_l;
    cudaGetSymbolAddress(&p, g_wa_h);  wa_h  = (bf16*)p;
    cudaGetSymbolAddress(&p, g_wa_l);  wa_l  = (bf16*)p;
    cudaGetSymbolAddress(&p, g_w1_h);  w1_h  = (bf16*)p;
    cudaGetSymbolAddress(&p, g_w1_l);  w1_l  = (bf16*)p;
    cudaGetSymbolAddress(&p, g_w2_h);  w2_h  = (bf16*)p;
    cudaGetSymbolAddress(&p, g_w2_l);  w2_l  = (bf16*)p;
    cudaGetSymbolAddress(&p, g_wal_h); wal_h = (bf16*)p;
    cudaGetSymbolAddress(&p, g_wal_l); wal_l = (bf16*)p;
    cudaGetSymbolAddress(&p, g_wm_h);  wm_h  = (bf16*)p;
    cudaGetSymbolAddress(&p, g_wm_l);  wm_l  = (bf16*)p;
    cudaGetSymbolAddress(&p, g_xs_h);  xs_h  = (bf16*)p;
    cudaGetSymbolAddress(&p, g_xs_l);  xs_l  = (bf16*)p;
    cudaGetSymbolAddress(&p, g_qk_h);  qk_h  = (bf16*)p;
    cudaGetSymbolAddress(&p, g_qk_l);  qk_l  = (bf16*)p;
    cudaGetSymbolAddress(&p, g_vs_h);  vs_h  = (bf16*)p;
    cudaGetSymbolAddress(&p, g_vs_l);  vs_l  = (bf16*)p;
    cudaGetSymbolAddress(&p, g_ss_h);  ss_h  = (bf16*)p;
    cudaGetSymbolAddress(&p, g_ss_l);  ss_l  = (bf16*)p;
    cudaGetSymbolAddress(&p, g_ts_h);  ts_h  = (bf16*)p;
    cudaGetSymbolAddress(&p, g_ts_l);  ts_l  = (bf16*)p;
    cudaGetSymbolAddress(&p, g_hs_h);  hs_h  = (bf16*)p;
    cudaGetSymbolAddress(&p, g_hs_l);  hs_l  = (bf16*)p;

    const float scl = 1.f / sqrtf((float)DH);
    const float* NOB = (const float*)0;
    float* NOC = (float*)0;
    bf16* NOS = (bf16*)0;
    dim3 tb(32, 8);

    // ---- weight transpose + split pre-passes ----
    tsplit_k<<<dim3(12, 12, 16), tb>>>(enc_attn_w, wa_h, wa_l, HD, HD);
    tsplit_k<<<dim3(12, 12, 16), tb>>>(dec_attn_w, wa_h + 16L*HD*HD, wa_l + 16L*HD*HD, HD, HD);
    tsplit_k<<<dim3(48, 36, 4), tb>>>(enc_c1w, w1_h, w1_l, KW*HD, HD2);
    tsplit_k<<<dim3(48, 36, 4), tb>>>(dec_c1w, w1_h + 4L*HD2*KW*HD, w1_l + 4L*HD2*KW*HD, KW*HD, HD2);
    tsplit_k<<<dim3(12, 144, 4), tb>>>(enc_c2w, w2_h, w2_l, KW*HD2, HD);
    tsplit_k<<<dim3(12, 144, 4), tb>>>(dec_c2w, w2_h + 4L*HD*KW*HD2, w2_l + 4L*HD*KW*HD2, KW*HD2, HD);
    tsplit_k<<<dim3(12, 36, 1), tb>>>(al_c1w, wal_h, wal_l, KW*HD, HD);
    tsplit_k<<<dim3(12, 36, 1), tb>>>(al_c2w, wal_h + (long)HD*KW*HD, wal_l + (long)HD*KW*HD, KW*HD, HD);
    tsplit_k<<<dim3(3, 12, 1), tb>>>(dec_lin_w, wm_h, wm_l, HD, MEL);

    embed_k<<<NB * NS, 128>>>(tokens, tok_emb, gx, xs_h, xs_l);

    auto fft_block = [&](float* xf, int T, int lidx, const float* ab,
                         const float* c1b, const float* c2b, const float* lnp) {
        long TH = (long)T * HD;
        const bf16* wah = wa_h + (long)lidx * 4 * HD * HD;
        const bf16* wal = wa_l + (long)lidx * 4 * HD * HD;
        // q,k projections -> split planes (z = 2*NB)
        gemm_bf<0,1><<<dim3(HD/128, T/128, 2*NB), 256, SMEM_BYTES>>>(
            xs_h, xs_l, NB, 0, TH, HD,
            wah, wal, (long)HD*HD, 0, HD,
            ab, HD,
            NOC, (long)NB*TH, TH, 0, 0,
            qk_h, qk_l, HD, T, HD, HD, 1.f, 0);
        // v projection -> transposed split planes [b][hd][t]
        gemm_bf<0,2><<<dim3(HD/128, T/128, NB), 256, SMEM_BYTES>>>(
            xs_h, xs_l, NB, 0, TH, HD,
            wah + 2L*HD*HD, wal + 2L*HD*HD, 0, 0, HD,
            ab + 2*HD, 0,
            NOC, 0, (long)HD*T, 0, 0,
            vs_h, vs_l, T, T, HD, HD, 1.f, 0);
        // scores = q @ k^T * scl  (fp32 out)
        gemm_bf<0,0><<<dim3(T/128, T/128, NB*NHEAD), 256, SMEM_BYTES>>>(
            qk_h, qk_l, NHEAD, TH, DH, HD,
            qk_h + (long)NB*TH, qk_l + (long)NB*TH, TH, DH, HD,
            NOB, 0,
            gsf, (long)NHEAD*T*T, (long)T*T, T, 1,
            NOS, NOS, 0, T, T, DH, scl, 0);
        softmax_k<<<NB * NHEAD * T, 256>>>(gsf, ss_h, ss_l, T);
        // attn @ V -> split planes gt  (N = DH = 192 -> 2 x-tiles)
        gemm_bf<0,1><<<dim3((DH + 127)/128, T/128, NB*NHEAD), 256, SMEM_BYTES>>>(
            ss_h, ss_l, NHEAD, (long)NHEAD*T*T, (long)T*T, T,
            vs_h, vs_l, (long)HD*T, (long)DH*T, T,
            NOB, 0,
            NOC, TH, DH, 0, 0,
            ts_h, ts_l, HD, T, DH, T, 1.f, 0);
        // output projection -> fp32 gu
        gemm_bf<0,0><<<dim3(HD/128, T/128, NB), 256, SMEM_BYTES>>>(
            ts_h, ts_l, NB, 0, TH, HD,
            wah + 3L*HD*HD, wal + 3L*HD*HD, 0, 0, HD,
            ab + 3*HD, 0,
            gu, 0, TH, HD, 1,
            NOS, NOS, 0, T, HD, HD, 1.f, 0);
        ln_k<<<NB * T, 128>>>(xf, gu, lnp + 0, lnp + HD, xf, xs_h, xs_l);
        // conv1 -> relu -> split planes gh
        gemm_bf<1,1><<<dim3(HD2/128, T/128, NB), 256, SMEM_BYTES>>>(
            xs_h, xs_l, NB, 0, TH, HD,
            w1_h + (long)lidx*HD2*KW*HD, w1_l + (long)lidx*HD2*KW*HD, 0, 0, KW*HD,
            c1b, 0,
            NOC, 0, (long)T*HD2, 0, 0,
            hs_h, hs_l, HD2, T, HD2, KW*HD, 1.f, 1);
        // conv2 -> fp32 gu
        gemm_bf<1,0><<<dim3(HD/128, T/128, NB), 256, SMEM_BYTES>>>(
            hs_h, hs_l, NB, 0, (long)T*HD2, HD2,
            w2_h + (long)lidx*HD*KW*HD2, w2_l + (long)lidx*HD*KW*HD2, 0, 0, KW*HD2,
            c2b, 0,
            gu, 0, TH, HD, 1,
            NOS, NOS, 0, T, HD, KW*HD2, 1.f, 0);
        ln_k<<<NB * T, 128>>>(xf, gu, lnp + 2*HD, lnp + 3*HD, xf, xs_h, xs_l);
    };

    // ---- encoder ----
    for (int l = 0; l < NLAY; l++)
        fft_block(gx, NS, l, enc_attn_b + (long)l*4*HD,
                  enc_c1b + (long)l*HD2, enc_c2b + (long)l*HD,
                  enc_ln + (long)l*4*HD);

    // ---- aligner ----
    {
        long TH = (long)NS * HD;
        gemm_bf<1,0><<<dim3(HD/128, NS/128, NB), 256, SMEM_BYTES>>>(
            xs_h, xs_l, NB, 0, TH, HD,
            wal_h, wal_l, 0, 0, KW*HD,
            al_c1b, 0,
            gha, 0, TH, HD, 1,
            NOS, NOS, 0, NS, HD, KW*HD, 1.f, 1);
        ln_k<<<NB * NS, 128>>>(gha, NOB, al_ln + 0, al_ln + HD, gha, ts_h, ts_l);
        gemm_bf<1,0><<<dim3(HD/128, NS/128, NB), 256, SMEM_BYTES>>>(
            ts_h, ts_l, NB, 0, TH, HD,
            wal_h + (long)HD*KW*HD, wal_l + (long)HD*KW*HD, 0, 0, KW*HD,
            al_c2b, 0,
            ghb, 0, TH, HD, 1,
            NOS, NOS, 0, NS, HD, KW*HD, 1.f, 1);
        ln_k<<<NB * NS, 128>>>(ghb, NOB, al_ln + 2*HD, al_ln + 3*HD, ghb, NOS, NOS);
        lin1_k<<<NB * NS, 128>>>(ghb, al_lin_w, al_lin_b, out_len);
    }

    // ---- length regulator ----
    cum_k<<<1, NB>>>(alignes32, gcum);
    expand_k<<<NB * TOUT, 128>>>(gx, gcum, gy, xs_h, xs_l);

    // ---- decoder ----
    for (int l = 0; l < NLAY; l++)
        fft_block(gy, TOUT, NLAY + l, dec_attn_b + (long)l*4*HD,
                  dec_c1b + (long)l*HD2, dec_c2b + (long)l*HD,
                  dec_ln + (long)l*4*HD);

    // ---- mel projection: out[b][n][t] (transposed fp32 write) ----
    gemm_bf<0,0><<<dim3(1, TOUT/128, NB), 256, SMEM_BYTES>>>(
        xs_h, xs_l, NB, 0, (long)TOUT*HD, HD,
        wm_h, wm_l, 0, 0, HD,
        dec_lin_b, 0,
        out, 0, (long)MEL*TOUT, 1, TOUT,
        NOS, NOS, 0, TOUT, MEL, HD, 1.f, 0);
}